// round 8
// baseline (speedup 1.0000x reference)
#include <cuda_runtime.h>
#include <math.h>

#define BB 8
#define SS 256
#define HH 100
#define PP 20
#define EPSF 1e-8f
#define NEGF 1e30f
typedef unsigned long long ull;

__device__ __forceinline__ ull pk2(float lo, float hi) {
    ull r; asm("mov.b64 %0, {%1,%2};" : "=l"(r) : "f"(lo), "f"(hi)); return r;
}
__device__ __forceinline__ void unpk2(ull v, float& lo, float& hi) {
    asm("mov.b64 {%0,%1}, %2;" : "=f"(lo), "=f"(hi) : "l"(v));
}
__device__ __forceinline__ ull fma2_(ull a, ull b, ull c) {
    ull d; asm("fma.rn.f32x2 %0, %1, %2, %3;" : "=l"(d) : "l"(a), "l"(b), "l"(c)); return d;
}

// ---------------- scratch -----------------------------------------------------
__device__ float g_c[2][BB][SS][HH];
__device__ float g_cT[2][BB][HH][SS];
__device__ float g_norm[2][BB][SS];
__device__ float g_npw[2][BB][SS][4 * PP];
__device__ float g_w2[4][PP][HH];
__device__ float g_last[2][BB][HH];
__device__ float g_nlast[2][BB];
__device__ float g_nlastw[2][BB][PP];
__device__ float g_len[2][BB];
__device__ float g_cos[BB][SS][SS];
__device__ float g_cosT[BB][SS][SS];
__device__ float g_cmax[2][BB][SS];
__device__ float g_cmean[2][BB][SS];
__device__ float g_csum[2][BB][SS];
__device__ float g_attmean[2][BB][SS][HH];
__device__ float g_attmax[2][BB][SS][HH];
__device__ float g_mpmax[2][BB][SS][PP];
__device__ float g_mpmean[2][BB][SS][PP];
__device__ float g_colmax[4][BB][PP][SS];
__device__ float g_colsum[4][BB][PP][SS];

// ---------------- K0: squared weights + lengths -------------------------------
__global__ void k_w2(const float* wf, const float* wm, const float* wa, const float* wx,
                     const int* mp, const int* mh) {
    int bx = blockIdx.x, t = threadIdx.x;
    if (bx < 4) {
        const float* w = (bx == 0) ? wf : (bx == 1) ? wm : (bx == 2) ? wa : wx;
        for (int idx = t; idx < PP * HH; idx += blockDim.x) {
            float v = w[idx];
            (&g_w2[bx][0][0])[idx] = v * v;
        }
    } else {
        int side = bx - 4;
        const int* msk = side ? mh : mp;
        int b = t >> 5, lane = t & 31;
        int s = 0;
#pragma unroll
        for (int k = 0; k < 8; k++) s += msk[b * SS + lane + 32 * k];
        for (int o = 16; o; o >>= 1) s += __shfl_xor_sync(0xffffffffu, s, o);
        if (lane == 0) g_len[side][b] = (float)s;
    }
}

// ---------------- K1a: mask + transpose + plain norms -------------------------
__global__ void k_prep1(const float* cp, const int* mp, const float* ch, const int* mh) {
    int side = blockIdx.y, r = blockIdx.x, b = r / SS, i = r % SS;
    const float* ctx = side ? ch : cp;
    const int* msk = side ? mh : mp;
    int t = threadIdx.x;
    float m = msk[r] ? 1.f : 0.f;
    float x = 0.f;
    if (t < HH) {
        x = ctx[r * HH + t] * m;
        g_c[side][b][i][t] = x;
        g_cT[side][b][t][i] = x;
    }
    float s = x * x;
    __shared__ float sw[4];
    for (int o = 16; o; o >>= 1) s += __shfl_xor_sync(0xffffffffu, s, o);
    if ((t & 31) == 0) sw[t >> 5] = s;
    __syncthreads();
    if (t == 0) g_norm[side][b][i] = sqrtf(sw[0] + sw[1] + sw[2] + sw[3]);
}

// ---------------- K1b: weighted norms (tiled smem matmul) ---------------------
__global__ void __launch_bounds__(128) k_prep2() {
    int gq = blockIdx.x, b = blockIdx.y, side = blockIdx.z;
    int i0 = gq * 16, t = threadIdx.x;
    __shared__ float sW[80][101];
    __shared__ float sX[16][101];
    const float* w2f = &g_w2[0][0][0];
    for (int idx = t; idx < 80 * HH; idx += 128) {
        int pr = idx / HH, h = idx % HH;
        sW[pr][h] = w2f[idx];
    }
    for (int idx = t; idx < 16 * HH; idx += 128) {
        int r = idx / HH, h = idx % HH;
        float x = g_c[side][b][i0 + r][h];
        sX[r][h] = x * x;
    }
    __syncthreads();
    for (int o = t; o < 1280; o += 128) {
        int pr = o % 80, r = o / 80;
        float s = 0.f;
#pragma unroll 4
        for (int h = 0; h < HH; h++) s += sW[pr][h] * sX[r][h];
        g_npw[side][b][i0 + r][pr] = sqrtf(s);
    }
}

// ---------------- K2: gather last valid token (g_len precomputed) -------------
__global__ void k_last() {
    int side = blockIdx.y, b = blockIdx.x, t = threadIdx.x;
    int len = (int)g_len[side][b];
    int idx = (len > 0) ? (len - 1) : 0;
    if (t < HH) g_last[side][b][t] = g_c[side][b][idx][t];
    if (t < PP) g_nlastw[side][b][t] = g_npw[side][b][idx][t];
    if (t == 127) g_nlast[side][b] = g_norm[side][b][idx];
}

// ---------------- K3: pairwise cosine GEMM (f32x2, 64x16, dup-B) --------------
__global__ void __launch_bounds__(128) k_cos() {
    int b = blockIdx.x, i0 = blockIdx.y * 64, j0 = blockIdx.z * 16;
    int t = threadIdx.x, tx = t & 7, ty = t >> 3;
    __shared__ ull sA[HH][34];
    __shared__ ull sBd[HH][18];
    __shared__ float sni[64], snj[16];
    for (int idx = t; idx < HH * 32; idx += 128) {
        int h = idx >> 5, ip = idx & 31;
        float2 v = *(const float2*)&g_cT[0][b][h][i0 + 2 * ip];
        sA[h][ip] = pk2(v.x, v.y);
    }
    for (int idx = t; idx < HH * 16; idx += 128) {
        int h = idx >> 4, j = idx & 15;
        float v = g_cT[1][b][h][j0 + j];
        sBd[h][j] = pk2(v, v);
    }
    if (t < 64) sni[t] = 1.f / fmaxf(g_norm[0][b][i0 + t], EPSF);
    if (t < 16) snj[t] = 1.f / fmaxf(g_norm[1][b][j0 + t], EPSF);
    __syncthreads();
    ull acc[2][2] = {0, 0, 0, 0};
#pragma unroll 4
    for (int h = 0; h < HH; h++) {
        ulonglong2 a = *(const ulonglong2*)&sA[h][ty * 2];
        ulonglong2 bd = *(const ulonglong2*)&sBd[h][tx * 2];
        acc[0][0] = fma2_(a.x, bd.x, acc[0][0]);
        acc[0][1] = fma2_(a.y, bd.x, acc[0][1]);
        acc[1][0] = fma2_(a.x, bd.y, acc[1][0]);
        acc[1][1] = fma2_(a.y, bd.y, acc[1][1]);
    }
#pragma unroll
    for (int jj = 0; jj < 2; jj++) {
        int j = j0 + tx * 2 + jj;
        float fj = snj[tx * 2 + jj];
#pragma unroll
        for (int rp = 0; rp < 2; rp++) {
            float dl, dh; unpk2(acc[jj][rp], dl, dh);
            int i = i0 + ty * 4 + rp * 2;
            float v0 = dl * sni[ty * 4 + rp * 2] * fj;
            float v1 = dh * sni[ty * 4 + rp * 2 + 1] * fj;
            g_cos[b][i][j] = v0;     g_cosT[b][j][i] = v0;
            g_cos[b][i + 1][j] = v1; g_cosT[b][j][i + 1] = v1;
        }
    }
}

// ---------------- K4: row reductions of cos (warp per row) --------------------
__global__ void __launch_bounds__(128) k_rowred(const int* mp, const int* mh) {
    int side = blockIdx.z, b = blockIdx.y;
    int t = threadIdx.x, w = t >> 5, lane = t & 31;
    int r = blockIdx.x * 4 + w;
    const float* row = side ? &g_cosT[b][r][0] : &g_cos[b][r][0];
    const int* omsk = side ? mp : mh;
    float vmax = -NEGF, vsum = 0.f;
#pragma unroll
    for (int k = 0; k < 8; k++) {
        int j = lane + 32 * k;
        float v = row[j];
        vsum += v;
        vmax = fmaxf(vmax, omsk[b * SS + j] ? v : -NEGF);
    }
    for (int o = 16; o; o >>= 1) {
        vmax = fmaxf(vmax, __shfl_xor_sync(0xffffffffu, vmax, o));
        vsum += __shfl_xor_sync(0xffffffffu, vsum, o);
    }
    if (lane == 0) {
        g_cmax[side][b][r] = vmax;
        g_csum[side][b][r] = vsum;
        g_cmean[side][b][r] = vsum / fmaxf(g_len[1 - side][b], EPSF);
    }
}

// ---------------- K5: attentive mean + max (8 rows/block, 512 blocks) ---------
__global__ void __launch_bounds__(128) k_att(const int* mp, const int* mh) {
    int gq = blockIdx.x, b = blockIdx.y, side = blockIdx.z;
    int i0 = gq * 8, t = threadIdx.x;
    __shared__ float satt[SS][12];   // [j][r], pad 12 -> 48B rows (16B aligned)
    __shared__ float sbias[SS];
    const int* omsk = side ? mp : mh;
    for (int idx = t; idx < 8 * SS; idx += 128) {
        int r = idx & 7, j = idx >> 3;
        satt[j][r] = side ? g_cosT[b][i0 + r][j] : g_cos[b][i0 + r][j];
    }
    for (int j = t; j < SS; j += 128)
        sbias[j] = omsk[b * SS + j] ? 0.f : -NEGF;
    __syncthreads();
    if (t < HH) {
        const float* oc = &g_c[1 - side][b][0][0];
        float mean[8], vmax[8];
#pragma unroll
        for (int r = 0; r < 8; r++) { mean[r] = 0.f; vmax[r] = -NEGF; }
#pragma unroll 2
        for (int j = 0; j < SS; j++) {
            float v = oc[j * HH + t];
            float bj = sbias[j];
            float4 a0 = *(const float4*)&satt[j][0];
            float4 a1 = *(const float4*)&satt[j][4];
            float a[8] = {a0.x, a0.y, a0.z, a0.w, a1.x, a1.y, a1.z, a1.w};
#pragma unroll
            for (int r = 0; r < 8; r++) {
                mean[r] = fmaf(a[r], v, mean[r]);
                vmax[r] = fmaxf(vmax[r], fmaf(a[r], v, bj));
            }
        }
#pragma unroll
        for (int r = 0; r < 8; r++) {
            int i = i0 + r;
            float denom = fmaxf(g_csum[side][b][i], EPSF);
            g_attmean[side][b][i][t] = mean[r] / denom;
            g_attmax[side][b][i][t] = vmax[r];
        }
    }
}

// ---------------- K6: maxpool multi-perspective GEMM (f32x2, 32-j tiles) ------
__global__ void __launch_bounds__(128) k_maxpool(const int* mp, const int* mh) {
    int p = blockIdx.x, b = blockIdx.y, ibl = blockIdx.z, i0 = ibl * 64;
    int t = threadIdx.x, tx = t & 7, ty = t >> 3;
    __shared__ ull sA[HH][34];           // 32 premultiplied i-pairs
    __shared__ ull sBd[HH][34];          // 32 dup-j entries
    __shared__ float sRedM[16][33], sRedS[16][33];
    __shared__ float sbJ[32], siJ[32];

    for (int idx = t; idx < HH * 32; idx += 128) {
        int h = idx >> 5, ip = idx & 31;
        float2 v = *(const float2*)&g_cT[0][b][h][i0 + 2 * ip];
        float w = g_w2[1][p][h];
        sA[h][ip] = pk2(v.x * w, v.y * w);
    }
    float invp[4], biasI[4], pmax[4], psum[4];
#pragma unroll
    for (int r = 0; r < 4; r++) {
        int i = i0 + ty * 4 + r;
        float n = g_npw[0][b][i][PP + p];
        int mi = mp[b * SS + i];
        invp[r] = (mi && n > 0.f) ? 1.f / n : 0.f;
        biasI[r] = mi ? 0.f : -NEGF;
        pmax[r] = -NEGF; psum[r] = 0.f;
    }
    float len_h = g_len[1][b];

    for (int jt = 0; jt < 8; jt++) {
        int j0 = jt * 32;
        __syncthreads();
        for (int idx = t; idx < HH * 32; idx += 128) {
            int h = idx >> 5, j = idx & 31;
            float v = g_cT[1][b][h][j0 + j];
            sBd[h][j] = pk2(v, v);
        }
        if (t < 32) {
            int j = j0 + t;
            float n = g_npw[1][b][j][PP + p];
            int mj = mh[b * SS + j];
            siJ[t] = (mj && n > 0.f) ? 1.f / n : 0.f;
            sbJ[t] = mj ? 0.f : -NEGF;
        }
        __syncthreads();

        ull acc[4][2] = {0, 0, 0, 0, 0, 0, 0, 0};
#pragma unroll 4
        for (int h = 0; h < HH; h++) {
            ulonglong2 a = *(const ulonglong2*)&sA[h][ty * 2];
            ulonglong2 b0 = *(const ulonglong2*)&sBd[h][tx * 4];
            ulonglong2 b1 = *(const ulonglong2*)&sBd[h][tx * 4 + 2];
            acc[0][0] = fma2_(a.x, b0.x, acc[0][0]); acc[0][1] = fma2_(a.y, b0.x, acc[0][1]);
            acc[1][0] = fma2_(a.x, b0.y, acc[1][0]); acc[1][1] = fma2_(a.y, b0.y, acc[1][1]);
            acc[2][0] = fma2_(a.x, b1.x, acc[2][0]); acc[2][1] = fma2_(a.y, b1.x, acc[2][1]);
            acc[3][0] = fma2_(a.x, b1.y, acc[3][0]); acc[3][1] = fma2_(a.y, b1.y, acc[3][1]);
        }
#pragma unroll
        for (int jj = 0; jj < 4; jj++) {
            int jl = tx * 4 + jj;
            float sj = siJ[jl], bj = sbJ[jl];
            float cm = -NEGF, cs = 0.f;
#pragma unroll
            for (int rp = 0; rp < 2; rp++) {
                float dl, dh; unpk2(acc[jj][rp], dl, dh);
                int r0 = rp * 2, r1 = rp * 2 + 1;
                float v0 = dl * sj; psum[r0] += v0; pmax[r0] = fmaxf(pmax[r0], v0 + bj);
                float v1 = dh * sj; psum[r1] += v1; pmax[r1] = fmaxf(pmax[r1], v1 + bj);
                float u0 = dl * invp[r0]; cs += u0; cm = fmaxf(cm, u0 + biasI[r0]);
                float u1 = dh * invp[r1]; cs += u1; cm = fmaxf(cm, u1 + biasI[r1]);
            }
            sRedM[ty][jl] = cm; sRedS[ty][jl] = cs;
        }
        __syncthreads();
        if (t < 32) {
            float m = -NEGF, s = 0.f;
#pragma unroll
            for (int k = 0; k < 16; k++) { m = fmaxf(m, sRedM[k][t]); s += sRedS[k][t]; }
            g_colmax[ibl][b][p][j0 + t] = m;
            g_colsum[ibl][b][p][j0 + t] = s;
        }
    }
#pragma unroll
    for (int r = 0; r < 4; r++) {
        float m = pmax[r], s = psum[r];
        for (int o = 4; o; o >>= 1) {
            m = fmaxf(m, __shfl_xor_sync(0xffffffffu, m, o));
            s += __shfl_xor_sync(0xffffffffu, s, o);
        }
        if (tx == 0) {
            int i = i0 + ty * 4 + r;
            g_mpmax[0][b][i][p] = m * invp[r];
            g_mpmean[0][b][i][p] = s * invp[r] / fmaxf(len_h, EPSF);
        }
    }
}

// ---------------- K6b: combine column partials --------------------------------
__global__ void k_mpc(const int* mh) {
    int p = blockIdx.x, b = blockIdx.y, j = threadIdx.x;
    float m = -NEGF, s = 0.f;
#pragma unroll
    for (int k = 0; k < 4; k++) {
        m = fmaxf(m, g_colmax[k][b][p][j]);
        s += g_colsum[k][b][p][j];
    }
    float n = g_npw[1][b][j][PP + p];
    int mj = mh[b * SS + j];
    float inv = (mj && n > 0.f) ? 1.f / n : 0.f;
    g_mpmax[1][b][j][p] = m * inv;
    g_mpmean[1][b][j][p] = s * inv / fmaxf(g_len[0][b], EPSF);
}

// ---------------- K7: assemble 105 outputs (8 rows/block) ---------------------
__global__ void __launch_bounds__(128) k_final(float* out) {
    int side = blockIdx.z, b = blockIdx.y, i0 = blockIdx.x * 8, t = threadIdx.x;
    __shared__ float sW[60][101];  // 0-19 w_full, 20-39 w_att, 40-59 w_maxatt
    __shared__ float sx[8][HH], sva[8][HH], svm[8][HH], sL[HH];
    __shared__ float sred[8][105];
    const float* w0 = &g_w2[0][0][0];
    const float* w2 = &g_w2[2][0][0];
    const float* w3 = &g_w2[3][0][0];
    for (int idx = t; idx < 20 * HH; idx += 128) {
        int pr = idx / HH, h = idx % HH;
        sW[pr][h] = w0[idx];
        sW[20 + pr][h] = w2[idx];
        sW[40 + pr][h] = w3[idx];
    }
    for (int idx = t; idx < 8 * HH; idx += 128) {
        int r = idx / HH, h = idx % HH;
        sx[r][h] = g_c[side][b][i0 + r][h];
        sva[r][h] = g_attmean[side][b][i0 + r][h];
        svm[r][h] = g_attmax[side][b][i0 + r][h];
    }
    if (t < HH) sL[t] = g_last[1 - side][b][t];
    __syncthreads();
    for (int o = t; o < 840; o += 128) {
        int r = o / 105, k = o % 105;
        float s = 0.f;
        if (k == 0)      { for (int h = 0; h < HH; h++) s += sx[r][h] * sL[h]; }
        else if (k == 1) { for (int h = 0; h < HH; h++) s += sx[r][h] * sva[r][h]; }
        else if (k == 2) { for (int h = 0; h < HH; h++) s += sx[r][h] * svm[r][h]; }
        else if (k == 3) { for (int h = 0; h < HH; h++) s += sva[r][h] * sva[r][h]; }
        else if (k == 4) { for (int h = 0; h < HH; h++) s += svm[r][h] * svm[r][h]; }
        else if (k < 25) { int p = k - 5;  for (int h = 0; h < HH; h++) s += sW[p][h] * sx[r][h] * sL[h]; }
        else if (k < 45) { int p = k - 25; for (int h = 0; h < HH; h++) s += sW[20 + p][h] * sx[r][h] * sva[r][h]; }
        else if (k < 65) { int p = k - 45; for (int h = 0; h < HH; h++) s += sW[20 + p][h] * sva[r][h] * sva[r][h]; }
        else if (k < 85) { int p = k - 65; for (int h = 0; h < HH; h++) s += sW[40 + p][h] * sx[r][h] * svm[r][h]; }
        else             { int p = k - 85; for (int h = 0; h < HH; h++) s += sW[40 + p][h] * svm[r][h] * svm[r][h]; }
        sred[r][k] = s;
    }
    __syncthreads();
    for (int o = t; o < 840; o += 128) {
        int r = o / 105, k = o % 105, i = i0 + r;
        float np = g_norm[side][b][i];
        float ov;
        if (k == 0)      ov = g_cmax[side][b][i];
        else if (k == 1) ov = g_cmean[side][b][i];
        else if (k == 2) ov = sred[r][0] / (fmaxf(np, EPSF) * fmaxf(g_nlast[1 - side][b], EPSF));
        else if (k < 23) {
            int p = k - 3;
            ov = sred[r][5 + p] / (fmaxf(g_npw[side][b][i][p], EPSF) * fmaxf(g_nlastw[1 - side][b][p], EPSF));
        }
        else if (k < 43) ov = g_mpmax[side][b][i][k - 23];
        else if (k < 63) ov = g_mpmean[side][b][i][k - 43];
        else if (k == 63) ov = sred[r][1] / (fmaxf(np, EPSF) * fmaxf(sqrtf(sred[r][3]), EPSF));
        else if (k < 84) {
            int p = k - 64;
            ov = sred[r][25 + p] / (fmaxf(g_npw[side][b][i][2 * PP + p], EPSF) * fmaxf(sqrtf(sred[r][45 + p]), EPSF));
        }
        else if (k == 84) ov = sred[r][2] / (fmaxf(np, EPSF) * fmaxf(sqrtf(sred[r][4]), EPSF));
        else {
            int p = k - 85;
            ov = sred[r][65 + p] / (fmaxf(g_npw[side][b][i][3 * PP + p], EPSF) * fmaxf(sqrtf(sred[r][85 + p]), EPSF));
        }
        out[((size_t)(side * BB + b) * SS + i) * 105 + k] = ov;
    }
}

// ---------------- launch ------------------------------------------------------
extern "C" void kernel_launch(void* const* d_in, const int* in_sizes, int n_in,
                              void* d_out, int out_size) {
    const float* ctx_p = (const float*)d_in[0];
    const int*   mp    = (const int*)d_in[1];
    const float* ctx_h = (const float*)d_in[2];
    const int*   mh    = (const int*)d_in[3];
    const float* wf    = (const float*)d_in[4];
    const float* wm    = (const float*)d_in[5];
    const float* wa    = (const float*)d_in[6];
    const float* wx    = (const float*)d_in[7];
    float* out = (float*)d_out;

    k_w2<<<6, 256>>>(wf, wm, wa, wx, mp, mh);
    k_prep1<<<dim3(BB * SS, 2), 128>>>(ctx_p, mp, ctx_h, mh);
    k_prep2<<<dim3(16, BB, 2), 128>>>();
    k_cos<<<dim3(BB, 4, 16), 128>>>();
    k_rowred<<<dim3(64, BB, 2), 128>>>(mp, mh);
    k_att<<<dim3(32, BB, 2), 128>>>(mp, mh);
    k_last<<<dim3(BB, 2), 128>>>();
    k_maxpool<<<dim3(PP, BB, 4), 128>>>(mp, mh);
    k_mpc<<<dim3(PP, BB), 256>>>(mh);
    k_final<<<dim3(32, BB, 2), 128>>>(out);
}

// round 9
// speedup vs baseline: 1.3012x; 1.3012x over previous
#include <cuda_runtime.h>
#include <math.h>

#define BB 8
#define SS 256
#define HH 100
#define PP 20
#define EPSF 1e-8f
#define NEGF 1e30f
typedef unsigned long long ull;

__device__ __forceinline__ ull pk2(float lo, float hi) {
    ull r; asm("mov.b64 %0, {%1,%2};" : "=l"(r) : "f"(lo), "f"(hi)); return r;
}
__device__ __forceinline__ void unpk2(ull v, float& lo, float& hi) {
    asm("mov.b64 {%0,%1}, %2;" : "=f"(lo), "=f"(hi) : "l"(v));
}
__device__ __forceinline__ ull fma2_(ull a, ull b, ull c) {
    ull d; asm("fma.rn.f32x2 %0, %1, %2, %3;" : "=l"(d) : "l"(a), "l"(b), "l"(c)); return d;
}

// ---------------- scratch -----------------------------------------------------
__device__ float g_c[2][BB][SS][HH];
__device__ float g_cT[2][BB][HH][SS];
__device__ float g_norm[2][BB][SS];
__device__ float g_npw[2][BB][SS][4 * PP];
__device__ float g_w2[4][PP][HH];
__device__ float g_last[2][BB][HH];
__device__ float g_nlast[2][BB];
__device__ float g_nlastw[2][BB][PP];
__device__ float g_len[2][BB];
__device__ float g_cos[BB][SS][SS];
__device__ float g_cosT[BB][SS][SS];
__device__ float g_cmax[2][BB][SS];
__device__ float g_cmean[2][BB][SS];
__device__ float g_csum[2][BB][SS];
__device__ float g_attmean[2][BB][SS][HH];
__device__ float g_attmax[2][BB][SS][HH];
__device__ float g_mpmax[2][BB][SS][PP];
__device__ float g_mpmean[2][BB][SS][PP];
__device__ float g_colmax[2][BB][PP][SS];
__device__ float g_colsum[2][BB][PP][SS];
__device__ float g_rowmax[4][BB][PP][SS];
__device__ float g_rowsum[4][BB][PP][SS];

// ---------------- K0: squared weights + lengths -------------------------------
__global__ void k_w2(const float* wf, const float* wm, const float* wa, const float* wx,
                     const int* mp, const int* mh) {
    int bx = blockIdx.x, t = threadIdx.x;
    if (bx < 4) {
        const float* w = (bx == 0) ? wf : (bx == 1) ? wm : (bx == 2) ? wa : wx;
        for (int idx = t; idx < PP * HH; idx += blockDim.x) {
            float v = w[idx];
            (&g_w2[bx][0][0])[idx] = v * v;
        }
    } else {
        int side = bx - 4;
        const int* msk = side ? mh : mp;
        int b = t >> 5, lane = t & 31;
        int s = 0;
#pragma unroll
        for (int k = 0; k < 8; k++) s += msk[b * SS + lane + 32 * k];
        for (int o = 16; o; o >>= 1) s += __shfl_xor_sync(0xffffffffu, s, o);
        if (lane == 0) g_len[side][b] = (float)s;
    }
}

// ---------------- K1a: mask + transpose + plain norms -------------------------
__global__ void k_prep1(const float* cp, const int* mp, const float* ch, const int* mh) {
    int side = blockIdx.y, r = blockIdx.x, b = r / SS, i = r % SS;
    const float* ctx = side ? ch : cp;
    const int* msk = side ? mh : mp;
    int t = threadIdx.x;
    float m = msk[r] ? 1.f : 0.f;
    float x = 0.f;
    if (t < HH) {
        x = ctx[r * HH + t] * m;
        g_c[side][b][i][t] = x;
        g_cT[side][b][t][i] = x;
    }
    float s = x * x;
    __shared__ float sw[4];
    for (int o = 16; o; o >>= 1) s += __shfl_xor_sync(0xffffffffu, s, o);
    if ((t & 31) == 0) sw[t >> 5] = s;
    __syncthreads();
    if (t == 0) g_norm[side][b][i] = sqrtf(sw[0] + sw[1] + sw[2] + sw[3]);
}

// ---------------- K1b: weighted norms (tiled smem matmul) ---------------------
__global__ void __launch_bounds__(128) k_prep2() {
    int gq = blockIdx.x, b = blockIdx.y, side = blockIdx.z;
    int i0 = gq * 16, t = threadIdx.x;
    __shared__ float sW[80][101];
    __shared__ float sX[16][101];
    const float* w2f = &g_w2[0][0][0];
    for (int idx = t; idx < 80 * HH; idx += 128) {
        int pr = idx / HH, h = idx % HH;
        sW[pr][h] = w2f[idx];
    }
    for (int idx = t; idx < 16 * HH; idx += 128) {
        int r = idx / HH, h = idx % HH;
        float x = g_c[side][b][i0 + r][h];
        sX[r][h] = x * x;
    }
    __syncthreads();
    for (int o = t; o < 1280; o += 128) {
        int pr = o % 80, r = o / 80;
        float s = 0.f;
#pragma unroll 4
        for (int h = 0; h < HH; h++) s += sW[pr][h] * sX[r][h];
        g_npw[side][b][i0 + r][pr] = sqrtf(s);
    }
}

// ---------------- K2: gather last valid token ---------------------------------
__global__ void k_last() {
    int side = blockIdx.y, b = blockIdx.x, t = threadIdx.x;
    int len = (int)g_len[side][b];
    int idx = (len > 0) ? (len - 1) : 0;
    if (t < HH) g_last[side][b][t] = g_c[side][b][idx][t];
    if (t < PP) g_nlastw[side][b][t] = g_npw[side][b][idx][t];
    if (t == 127) g_nlast[side][b] = g_norm[side][b][idx];
}

// ---------------- K3: pairwise cosine GEMM (f32x2, 64x16, dup-B) --------------
__global__ void __launch_bounds__(128) k_cos() {
    int b = blockIdx.x, i0 = blockIdx.y * 64, j0 = blockIdx.z * 16;
    int t = threadIdx.x, tx = t & 7, ty = t >> 3;
    __shared__ ull sA[HH][34];
    __shared__ ull sBd[HH][18];
    __shared__ float sni[64], snj[16];
    for (int idx = t; idx < HH * 32; idx += 128) {
        int h = idx >> 5, ip = idx & 31;
        float2 v = *(const float2*)&g_cT[0][b][h][i0 + 2 * ip];
        sA[h][ip] = pk2(v.x, v.y);
    }
    for (int idx = t; idx < HH * 16; idx += 128) {
        int h = idx >> 4, j = idx & 15;
        float v = g_cT[1][b][h][j0 + j];
        sBd[h][j] = pk2(v, v);
    }
    if (t < 64) sni[t] = 1.f / fmaxf(g_norm[0][b][i0 + t], EPSF);
    if (t < 16) snj[t] = 1.f / fmaxf(g_norm[1][b][j0 + t], EPSF);
    __syncthreads();
    ull acc[2][2] = {0, 0, 0, 0};
#pragma unroll 4
    for (int h = 0; h < HH; h++) {
        ulonglong2 a = *(const ulonglong2*)&sA[h][ty * 2];
        ulonglong2 bd = *(const ulonglong2*)&sBd[h][tx * 2];
        acc[0][0] = fma2_(a.x, bd.x, acc[0][0]);
        acc[0][1] = fma2_(a.y, bd.x, acc[0][1]);
        acc[1][0] = fma2_(a.x, bd.y, acc[1][0]);
        acc[1][1] = fma2_(a.y, bd.y, acc[1][1]);
    }
#pragma unroll
    for (int jj = 0; jj < 2; jj++) {
        int j = j0 + tx * 2 + jj;
        float fj = snj[tx * 2 + jj];
#pragma unroll
        for (int rp = 0; rp < 2; rp++) {
            float dl, dh; unpk2(acc[jj][rp], dl, dh);
            int i = i0 + ty * 4 + rp * 2;
            float v0 = dl * sni[ty * 4 + rp * 2] * fj;
            float v1 = dh * sni[ty * 4 + rp * 2 + 1] * fj;
            g_cos[b][i][j] = v0;     g_cosT[b][j][i] = v0;
            g_cos[b][i + 1][j] = v1; g_cosT[b][j][i + 1] = v1;
        }
    }
}

// ---------------- K4: row reductions of cos (warp per row) --------------------
__global__ void __launch_bounds__(128) k_rowred(const int* mp, const int* mh) {
    int side = blockIdx.z, b = blockIdx.y;
    int t = threadIdx.x, w = t >> 5, lane = t & 31;
    int r = blockIdx.x * 4 + w;
    const float* row = side ? &g_cosT[b][r][0] : &g_cos[b][r][0];
    const int* omsk = side ? mp : mh;
    float vmax = -NEGF, vsum = 0.f;
#pragma unroll
    for (int k = 0; k < 8; k++) {
        int j = lane + 32 * k;
        float v = row[j];
        vsum += v;
        vmax = fmaxf(vmax, omsk[b * SS + j] ? v : -NEGF);
    }
    for (int o = 16; o; o >>= 1) {
        vmax = fmaxf(vmax, __shfl_xor_sync(0xffffffffu, vmax, o));
        vsum += __shfl_xor_sync(0xffffffffu, vsum, o);
    }
    if (lane == 0) {
        g_cmax[side][b][r] = vmax;
        g_csum[side][b][r] = vsum;
        g_cmean[side][b][r] = vsum / fmaxf(g_len[1 - side][b], EPSF);
    }
}

// ---------------- K5: attentive mean + max (8 rows/block, 512 blocks) ---------
__global__ void __launch_bounds__(128) k_att(const int* mp, const int* mh) {
    int gq = blockIdx.x, b = blockIdx.y, side = blockIdx.z;
    int i0 = gq * 8, t = threadIdx.x;
    __shared__ float satt[SS][12];
    __shared__ float sbias[SS];
    const int* omsk = side ? mp : mh;
    for (int idx = t; idx < 8 * SS; idx += 128) {
        int r = idx & 7, j = idx >> 3;
        satt[j][r] = side ? g_cosT[b][i0 + r][j] : g_cos[b][i0 + r][j];
    }
    for (int j = t; j < SS; j += 128)
        sbias[j] = omsk[b * SS + j] ? 0.f : -NEGF;
    __syncthreads();
    if (t < HH) {
        const float* oc = &g_c[1 - side][b][0][0];
        float mean[8], vmax[8];
#pragma unroll
        for (int r = 0; r < 8; r++) { mean[r] = 0.f; vmax[r] = -NEGF; }
#pragma unroll 2
        for (int j = 0; j < SS; j++) {
            float v = oc[j * HH + t];
            float bj = sbias[j];
            float4 a0 = *(const float4*)&satt[j][0];
            float4 a1 = *(const float4*)&satt[j][4];
            float a[8] = {a0.x, a0.y, a0.z, a0.w, a1.x, a1.y, a1.z, a1.w};
#pragma unroll
            for (int r = 0; r < 8; r++) {
                mean[r] = fmaf(a[r], v, mean[r]);
                vmax[r] = fmaxf(vmax[r], fmaf(a[r], v, bj));
            }
        }
#pragma unroll
        for (int r = 0; r < 8; r++) {
            int i = i0 + r;
            float denom = fmaxf(g_csum[side][b][i], EPSF);
            g_attmean[side][b][i][t] = mean[r] / denom;
            g_attmax[side][b][i][t] = vmax[r];
        }
    }
}

// ---------------- K6: maxpool GEMM, occupancy-oriented ------------------------
// grid (PP, BB, 8): z = ibl*4 + jbl; block 256 = tx8 x ty32
// block tile: 128 i x 64 j (2 jt of 32); per thread 4i x 4j; h-chunks of 50
__global__ void __launch_bounds__(256) k_maxpool(const int* mp, const int* mh) {
    int p = blockIdx.x, b = blockIdx.y;
    int ibl = blockIdx.z >> 2, jbl = blockIdx.z & 3;
    int i0 = ibl * 128, j0 = jbl * 64;
    int t = threadIdx.x, tx = t & 7, ty = t >> 3;
    __shared__ ull sA[50][66];      // 64 premultiplied i-pairs per h
    __shared__ ull sBd[50][34];     // 32 dup-j per h (one jt)
    __shared__ float sRedM[32][33], sRedS[32][33];
    __shared__ float siJ[64], sbJ[64];

    if (t < 64) {
        int j = j0 + t;
        float n = g_npw[1][b][j][PP + p];
        int mj = mh[b * SS + j];
        siJ[t] = (mj && n > 0.f) ? 1.f / n : 0.f;
        sbJ[t] = mj ? 0.f : -NEGF;
    }
    float invp[4], biasI[4];
#pragma unroll
    for (int r = 0; r < 4; r++) {
        int i = i0 + ty * 4 + r;
        float n = g_npw[0][b][i][PP + p];
        int mi = mp[b * SS + i];
        invp[r] = (mi && n > 0.f) ? 1.f / n : 0.f;
        biasI[r] = mi ? 0.f : -NEGF;
    }
    ull acc[2][4][2];
#pragma unroll
    for (int jt = 0; jt < 2; jt++)
#pragma unroll
        for (int jj = 0; jj < 4; jj++) { acc[jt][jj][0] = 0; acc[jt][jj][1] = 0; }

#pragma unroll
    for (int hc = 0; hc < 2; hc++) {
        int hb = hc * 50;
        __syncthreads();
        for (int idx = t; idx < 50 * 64; idx += 256) {
            int hh = idx >> 6, ip = idx & 63;
            int h = hb + hh;
            float2 v = *(const float2*)&g_cT[0][b][h][i0 + 2 * ip];
            float w = g_w2[1][p][h];
            sA[hh][ip] = pk2(v.x * w, v.y * w);
        }
#pragma unroll
        for (int jt = 0; jt < 2; jt++) {
            if (jt) __syncthreads();
            for (int idx = t; idx < 50 * 32; idx += 256) {
                int hh = idx >> 5, j = idx & 31;
                float v = g_cT[1][b][hb + hh][j0 + jt * 32 + j];
                sBd[hh][j] = pk2(v, v);
            }
            __syncthreads();
#pragma unroll 5
            for (int hh = 0; hh < 50; hh++) {
                ulonglong2 a2 = *(const ulonglong2*)&sA[hh][ty * 2];
                ulonglong2 b0 = *(const ulonglong2*)&sBd[hh][tx * 2];
                ulonglong2 b1 = *(const ulonglong2*)&sBd[hh][tx * 2 + 16];
                acc[jt][0][0] = fma2_(a2.x, b0.x, acc[jt][0][0]);
                acc[jt][0][1] = fma2_(a2.y, b0.x, acc[jt][0][1]);
                acc[jt][1][0] = fma2_(a2.x, b0.y, acc[jt][1][0]);
                acc[jt][1][1] = fma2_(a2.y, b0.y, acc[jt][1][1]);
                acc[jt][2][0] = fma2_(a2.x, b1.x, acc[jt][2][0]);
                acc[jt][2][1] = fma2_(a2.y, b1.x, acc[jt][2][1]);
                acc[jt][3][0] = fma2_(a2.x, b1.y, acc[jt][3][0]);
                acc[jt][3][1] = fma2_(a2.y, b1.y, acc[jt][3][1]);
            }
        }
    }

    float pmaxr[4], psumr[4];
#pragma unroll
    for (int r = 0; r < 4; r++) { pmaxr[r] = -NEGF; psumr[r] = 0.f; }
#pragma unroll
    for (int jt = 0; jt < 2; jt++) {
        __syncthreads();
#pragma unroll
        for (int jj = 0; jj < 4; jj++) {
            int jl = 2 * tx + (jj & 1) + ((jj >> 1) << 4);  // {2tx,2tx+1,2tx+16,2tx+17}
            int jg = jt * 32 + jl;
            float sj = siJ[jg], bj = sbJ[jg];
            float cm = -NEGF, cs = 0.f;
#pragma unroll
            for (int rp = 0; rp < 2; rp++) {
                float dl, dh; unpk2(acc[jt][jj][rp], dl, dh);
                int r0 = rp * 2, r1 = rp * 2 + 1;
                float v0 = dl * sj; psumr[r0] += v0; pmaxr[r0] = fmaxf(pmaxr[r0], v0 + bj);
                float v1 = dh * sj; psumr[r1] += v1; pmaxr[r1] = fmaxf(pmaxr[r1], v1 + bj);
                float u0 = dl * invp[r0]; cs += u0; cm = fmaxf(cm, u0 + biasI[r0]);
                float u1 = dh * invp[r1]; cs += u1; cm = fmaxf(cm, u1 + biasI[r1]);
            }
            sRedM[ty][jl] = cm; sRedS[ty][jl] = cs;
        }
        __syncthreads();
        if (t < 32) {
            float m = -NEGF, s = 0.f;
#pragma unroll
            for (int k = 0; k < 32; k++) { m = fmaxf(m, sRedM[k][t]); s += sRedS[k][t]; }
            g_colmax[ibl][b][p][j0 + jt * 32 + t] = m;
            g_colsum[ibl][b][p][j0 + jt * 32 + t] = s;
        }
    }
#pragma unroll
    for (int r = 0; r < 4; r++) {
        float m = pmaxr[r], s = psumr[r];
        for (int o = 4; o; o >>= 1) {
            m = fmaxf(m, __shfl_xor_sync(0xffffffffu, m, o));
            s += __shfl_xor_sync(0xffffffffu, s, o);
        }
        if (tx == 0) {
            int i = i0 + ty * 4 + r;
            g_rowmax[jbl][b][p][i] = m;
            g_rowsum[jbl][b][p][i] = s;
        }
    }
}

// ---------------- K6b: combine partials (both directions) ---------------------
__global__ void k_mpc(const int* mp, const int* mh) {
    int p = blockIdx.x, b = blockIdx.y, t = threadIdx.x;  // 256 threads
    {   // columns (side 1, per j): combine 2 ibl
        float m = fmaxf(g_colmax[0][b][p][t], g_colmax[1][b][p][t]);
        float s = g_colsum[0][b][p][t] + g_colsum[1][b][p][t];
        float n = g_npw[1][b][t][PP + p];
        int mj = mh[b * SS + t];
        float inv = (mj && n > 0.f) ? 1.f / n : 0.f;
        g_mpmax[1][b][t][p] = m * inv;
        g_mpmean[1][b][t][p] = s * inv / fmaxf(g_len[0][b], EPSF);
    }
    {   // rows (side 0, per i): combine 4 jbl
        float m = g_rowmax[0][b][p][t], s = g_rowsum[0][b][p][t];
#pragma unroll
        for (int k = 1; k < 4; k++) {
            m = fmaxf(m, g_rowmax[k][b][p][t]);
            s += g_rowsum[k][b][p][t];
        }
        float n = g_npw[0][b][t][PP + p];
        int mi = mp[b * SS + t];
        float inv = (mi && n > 0.f) ? 1.f / n : 0.f;
        g_mpmax[0][b][t][p] = m * inv;
        g_mpmean[0][b][t][p] = s * inv / fmaxf(g_len[1][b], EPSF);
    }
}

// ---------------- K7: assemble 105 outputs (8 rows/block) ---------------------
__global__ void __launch_bounds__(128) k_final(float* out) {
    int side = blockIdx.z, b = blockIdx.y, i0 = blockIdx.x * 8, t = threadIdx.x;
    __shared__ float sW[60][101];
    __shared__ float sx[8][HH], sva[8][HH], svm[8][HH], sL[HH];
    __shared__ float sred[8][105];
    const float* w0 = &g_w2[0][0][0];
    const float* w2 = &g_w2[2][0][0];
    const float* w3 = &g_w2[3][0][0];
    for (int idx = t; idx < 20 * HH; idx += 128) {
        int pr = idx / HH, h = idx % HH;
        sW[pr][h] = w0[idx];
        sW[20 + pr][h] = w2[idx];
        sW[40 + pr][h] = w3[idx];
    }
    for (int idx = t; idx < 8 * HH; idx += 128) {
        int r = idx / HH, h = idx % HH;
        sx[r][h] = g_c[side][b][i0 + r][h];
        sva[r][h] = g_attmean[side][b][i0 + r][h];
        svm[r][h] = g_attmax[side][b][i0 + r][h];
    }
    if (t < HH) sL[t] = g_last[1 - side][b][t];
    __syncthreads();
    for (int o = t; o < 840; o += 128) {
        int r = o / 105, k = o % 105;
        float s = 0.f;
        if (k == 0)      { for (int h = 0; h < HH; h++) s += sx[r][h] * sL[h]; }
        else if (k == 1) { for (int h = 0; h < HH; h++) s += sx[r][h] * sva[r][h]; }
        else if (k == 2) { for (int h = 0; h < HH; h++) s += sx[r][h] * svm[r][h]; }
        else if (k == 3) { for (int h = 0; h < HH; h++) s += sva[r][h] * sva[r][h]; }
        else if (k == 4) { for (int h = 0; h < HH; h++) s += svm[r][h] * svm[r][h]; }
        else if (k < 25) { int p = k - 5;  for (int h = 0; h < HH; h++) s += sW[p][h] * sx[r][h] * sL[h]; }
        else if (k < 45) { int p = k - 25; for (int h = 0; h < HH; h++) s += sW[20 + p][h] * sx[r][h] * sva[r][h]; }
        else if (k < 65) { int p = k - 45; for (int h = 0; h < HH; h++) s += sW[20 + p][h] * sva[r][h] * sva[r][h]; }
        else if (k < 85) { int p = k - 65; for (int h = 0; h < HH; h++) s += sW[40 + p][h] * sx[r][h] * svm[r][h]; }
        else             { int p = k - 85; for (int h = 0; h < HH; h++) s += sW[40 + p][h] * svm[r][h] * svm[r][h]; }
        sred[r][k] = s;
    }
    __syncthreads();
    for (int o = t; o < 840; o += 128) {
        int r = o / 105, k = o % 105, i = i0 + r;
        float np = g_norm[side][b][i];
        float ov;
        if (k == 0)      ov = g_cmax[side][b][i];
        else if (k == 1) ov = g_cmean[side][b][i];
        else if (k == 2) ov = sred[r][0] / (fmaxf(np, EPSF) * fmaxf(g_nlast[1 - side][b], EPSF));
        else if (k < 23) {
            int p = k - 3;
            ov = sred[r][5 + p] / (fmaxf(g_npw[side][b][i][p], EPSF) * fmaxf(g_nlastw[1 - side][b][p], EPSF));
        }
        else if (k < 43) ov = g_mpmax[side][b][i][k - 23];
        else if (k < 63) ov = g_mpmean[side][b][i][k - 43];
        else if (k == 63) ov = sred[r][1] / (fmaxf(np, EPSF) * fmaxf(sqrtf(sred[r][3]), EPSF));
        else if (k < 84) {
            int p = k - 64;
            ov = sred[r][25 + p] / (fmaxf(g_npw[side][b][i][2 * PP + p], EPSF) * fmaxf(sqrtf(sred[r][45 + p]), EPSF));
        }
        else if (k == 84) ov = sred[r][2] / (fmaxf(np, EPSF) * fmaxf(sqrtf(sred[r][4]), EPSF));
        else {
            int p = k - 85;
            ov = sred[r][65 + p] / (fmaxf(g_npw[side][b][i][3 * PP + p], EPSF) * fmaxf(sqrtf(sred[r][85 + p]), EPSF));
        }
        out[((size_t)(side * BB + b) * SS + i) * 105 + k] = ov;
    }
}

// ---------------- launch ------------------------------------------------------
extern "C" void kernel_launch(void* const* d_in, const int* in_sizes, int n_in,
                              void* d_out, int out_size) {
    const float* ctx_p = (const float*)d_in[0];
    const int*   mp    = (const int*)d_in[1];
    const float* ctx_h = (const float*)d_in[2];
    const int*   mh    = (const int*)d_in[3];
    const float* wf    = (const float*)d_in[4];
    const float* wm    = (const float*)d_in[5];
    const float* wa    = (const float*)d_in[6];
    const float* wx    = (const float*)d_in[7];
    float* out = (float*)d_out;

    k_w2<<<6, 256>>>(wf, wm, wa, wx, mp, mh);
    k_prep1<<<dim3(BB * SS, 2), 128>>>(ctx_p, mp, ctx_h, mh);
    k_prep2<<<dim3(16, BB, 2), 128>>>();
    k_maxpool<<<dim3(PP, BB, 8), 256>>>(mp, mh);
    k_cos<<<dim3(BB, 4, 16), 128>>>();
    k_rowred<<<dim3(64, BB, 2), 128>>>(mp, mh);
    k_att<<<dim3(32, BB, 2), 128>>>(mp, mh);
    k_last<<<dim3(BB, 2), 128>>>();
    k_mpc<<<dim3(PP, BB), 256>>>(mp, mh);
    k_final<<<dim3(32, BB, 2), 128>>>(out);
}